// round 6
// baseline (speedup 1.0000x reference)
#include <cuda_runtime.h>
#include <cstdint>

// Problem constants (fixed by the reference setup)
static constexpr int   N_PER_TABLE = 2097152;          // indices/weights per table
static constexpr int   B_PER_TABLE = 8192;             // offsets used per table (input len B+1)
static constexpr int   T_TABLES    = 8;
static constexpr long long IDX_TOT = (long long)T_TABLES * N_PER_TABLE;     // 16777216
static constexpr long long OFF_TOT = (long long)T_TABLES * B_PER_TABLE + 1; // 65537
static constexpr int   NVEC        = N_PER_TABLE / 4;  // int4 groups per table = 524288
static constexpr int   NVEC_LOG2   = 19;               // log2(524288)

struct TablePtrs {
    const int4*   idx[T_TABLES];
    const int*    off[T_TABLES];
    const float4* w[T_TABLES];
};

__global__ void __launch_bounds__(256)
tbe_prepare_kernel(TablePtrs p, float* __restrict__ out) {
    // Output is ONE float32 buffer: [indices as float | offsets as float | weights]
    float4* out_idx = reinterpret_cast<float4*>(out);            // base 256B-aligned
    float*  out_off = out + IDX_TOT;
    float*  out_w   = out + IDX_TOT + OFF_TOT;                   // byte offset ≡ 4 mod 16

    const long long tid    = (long long)blockIdx.x * blockDim.x + threadIdx.x;
    const long long stride = (long long)gridDim.x * blockDim.x;
    const long long TOTAL_VEC = (long long)T_TABLES * NVEC;      // 4194304

    // ---- indices: int4 load, convert to float (exact, values < 2^24), float4 store ----
    for (long long i = tid; i < TOTAL_VEC; i += stride) {
        const int t = (int)(i >> NVEC_LOG2);
        const long long j = i & (NVEC - 1);
        const int4 v = p.idx[t][j];
        float4 f;
        f.x = (float)v.x;
        f.y = (float)v.y;
        f.z = (float)v.z;
        f.w = (float)v.w;
        out_idx[i] = f;
    }

    // ---- weights: float4 load (src 16B-aligned), 4x scalar store (dst ≡ 4 mod 16) ----
    for (long long i = tid; i < TOTAL_VEC; i += stride) {
        const int t = (int)(i >> NVEC_LOG2);
        const long long j = i & (NVEC - 1);
        const float4 v = p.w[t][j];
        const long long base = i << 2;
        out_w[base + 0] = v.x;
        out_w[base + 1] = v.y;
        out_w[base + 2] = v.z;
        out_w[base + 3] = v.w;
    }

    // ---- offsets: first B entries per table, rebased by t*N, stored as float ----
    const long long OFF_WORK = (long long)T_TABLES * B_PER_TABLE;   // 65536
    for (long long i = tid; i < OFF_WORK; i += stride) {
        const int t = (int)(i >> 13);            // / 8192
        const int j = (int)(i & (B_PER_TABLE - 1));
        out_off[i] = (float)(p.off[t][j] + t * N_PER_TABLE);
    }
    if (tid == 0) {
        out_off[OFF_WORK] = (float)IDX_TOT;      // grand total sentinel (2^24, exact in fp32)
    }
}

extern "C" void kernel_launch(void* const* d_in, const int* in_sizes, int n_in,
                              void* d_out, int out_size) {
    (void)out_size;

    TablePtrs p;

    // Detect input ordering at runtime via the distinctive offsets length (B+1 = 8193).
    // Grouped  (reference signature order): indices_0..7, offsets_0..7, weights_0..7
    // Interleaved (setup_inputs dict order): indices_0, offsets_0, weights_0, indices_1, ...
    const bool grouped = (n_in >= 24) && (in_sizes[8] == B_PER_TABLE + 1);

    if (grouped) {
        for (int t = 0; t < T_TABLES; ++t) {
            p.idx[t] = reinterpret_cast<const int4*>(d_in[t]);
            p.off[t] = reinterpret_cast<const int*>(d_in[T_TABLES + t]);
            p.w[t]   = reinterpret_cast<const float4*>(d_in[2 * T_TABLES + t]);
        }
    } else {
        for (int t = 0; t < T_TABLES; ++t) {
            p.idx[t] = reinterpret_cast<const int4*>(d_in[3 * t + 0]);
            p.off[t] = reinterpret_cast<const int*>(d_in[3 * t + 1]);
            p.w[t]   = reinterpret_cast<const float4*>(d_in[3 * t + 2]);
        }
    }

    float* out = reinterpret_cast<float*>(d_out);

    // 2048 blocks x 256 threads = 524288 threads; ~8 iterations per loop per thread.
    // Deep MLP per thread + full-chip occupancy to saturate HBM3e.
    tbe_prepare_kernel<<<2048, 256>>>(p, out);
}

// round 8
// speedup vs baseline: 1.0351x; 1.0351x over previous
#include <cuda_runtime.h>
#include <cstdint>

// Problem constants (fixed by the reference setup)
static constexpr int   N_PER_TABLE = 2097152;          // indices/weights per table (2^21)
static constexpr int   B_PER_TABLE = 8192;             // offsets used per table (input len B+1)
static constexpr int   T_TABLES    = 8;
static constexpr long long IDX_TOT = (long long)T_TABLES * N_PER_TABLE;     // 16777216
static constexpr long long OFF_TOT = (long long)T_TABLES * B_PER_TABLE + 1; // 65537
static constexpr int   NVEC        = N_PER_TABLE / 4;  // int4 groups per table = 524288
static constexpr int   NVEC_LOG2   = 19;               // log2(524288)
static constexpr int   N_LOG2      = 21;               // log2(N_PER_TABLE)

static constexpr int   GRID    = 2048;
static constexpr int   BLOCK   = 256;
static constexpr long long NTHREADS = (long long)GRID * BLOCK;           // 524288
static constexpr long long TOTAL_VEC = (long long)T_TABLES * NVEC;       // 4194304 = 8*NTHREADS
static constexpr int   VPT     = (int)(TOTAL_VEC / NTHREADS);            // 8 vectors/thread
static constexpr long long W_TOT = IDX_TOT;                              // 16777216 weights
// Aligned-store weight vectors: elements [3, W_TOT-1) in 4-wide groups
static constexpr long long WVEC  = (W_TOT - 4) / 4;                      // 4194303 full vectors

struct TablePtrs {
    const int4*  idx[T_TABLES];
    const int*   off[T_TABLES];
    const float* w[T_TABLES];
};

__global__ void __launch_bounds__(BLOCK)
tbe_prepare_kernel(TablePtrs p, float* __restrict__ out) {
    // Output: ONE float32 buffer [indices-as-float | offsets-as-float | weights]
    float4* out_idx = reinterpret_cast<float4*>(out);       // 256B-aligned base
    float*  out_off = out + IDX_TOT;
    float*  out_w   = out + IDX_TOT + OFF_TOT;              // byte addr ≡ 4 (mod 16)
    float4* out_w_v = reinterpret_cast<float4*>(out_w + 3); // 16B-aligned

    const long long tid = (long long)blockIdx.x * BLOCK + threadIdx.x;

    // ---- indices: batched int4 loads -> exact I2F -> float4 streaming stores ----
    #pragma unroll
    for (int u = 0; u < VPT; u += 4) {
        int4 v[4];
        #pragma unroll
        for (int q = 0; q < 4; ++q) {
            const long long i = (long long)(u + q) * NTHREADS + tid;
            const int t = (int)(i >> NVEC_LOG2);
            const long long j = i & (NVEC - 1);
            v[q] = __ldcs(&p.idx[t][j]);
        }
        #pragma unroll
        for (int q = 0; q < 4; ++q) {
            const long long i = (long long)(u + q) * NTHREADS + tid;
            float4 f;
            f.x = (float)v[q].x;  f.y = (float)v[q].y;
            f.z = (float)v[q].z;  f.w = (float)v[q].w;
            __stcs(&out_idx[i], f);
        }
    }

    // ---- weights: 4 scalar streaming loads -> one aligned float4 streaming store ----
    // Store vector k covers output weight elements [3+4k, 7+4k); source element g may
    // cross a table boundary, so each scalar resolves its own (t, j).
    #pragma unroll
    for (int u = 0; u < VPT; u += 4) {
        float4 v[4];
        #pragma unroll
        for (int q = 0; q < 4; ++q) {
            const long long k = (long long)(u + q) * NTHREADS + tid;
            if (k < WVEC) {
                const long long g = 3 + (k << 2);
                #pragma unroll
                for (int e = 0; e < 4; ++e) {
                    const long long ge = g + e;
                    const int t = (int)(ge >> N_LOG2);
                    const long long j = ge & (N_PER_TABLE - 1);
                    (&v[q].x)[e] = __ldcs(&p.w[t][j]);
                }
            }
        }
        #pragma unroll
        for (int q = 0; q < 4; ++q) {
            const long long k = (long long)(u + q) * NTHREADS + tid;
            if (k < WVEC) __stcs(&out_w_v[k], v[q]);
        }
    }

    // ---- weight prologue (elements 0..2) + tail (element W_TOT-1) ----
    if (tid < 3) {
        out_w[tid] = __ldcs(&p.w[0][tid]);
    } else if (tid == 3) {
        out_w[W_TOT - 1] = __ldcs(&p.w[T_TABLES - 1][N_PER_TABLE - 1]);
    }

    // ---- offsets: first B entries per table, rebased by t*N, stored as float ----
    const long long OFF_WORK = (long long)T_TABLES * B_PER_TABLE;   // 65536
    if (tid < OFF_WORK) {
        const int t = (int)(tid >> 13);            // / 8192
        const int j = (int)(tid & (B_PER_TABLE - 1));
        out_off[tid] = (float)(p.off[t][j] + t * N_PER_TABLE);
    }
    if (tid == 0) {
        out_off[OFF_WORK] = (float)IDX_TOT;        // grand total (2^24, exact in fp32)
    }
}

extern "C" void kernel_launch(void* const* d_in, const int* in_sizes, int n_in,
                              void* d_out, int out_size) {
    (void)out_size;

    TablePtrs p;

    // Runtime layout detection via the distinctive offsets length (B+1 = 8193).
    // Grouped:     indices_0..7, offsets_0..7, weights_0..7
    // Interleaved: indices_0, offsets_0, weights_0, indices_1, ...
    const bool grouped = (n_in >= 24) && (in_sizes[8] == B_PER_TABLE + 1);

    if (grouped) {
        for (int t = 0; t < T_TABLES; ++t) {
            p.idx[t] = reinterpret_cast<const int4*>(d_in[t]);
            p.off[t] = reinterpret_cast<const int*>(d_in[T_TABLES + t]);
            p.w[t]   = reinterpret_cast<const float*>(d_in[2 * T_TABLES + t]);
        }
    } else {
        for (int t = 0; t < T_TABLES; ++t) {
            p.idx[t] = reinterpret_cast<const int4*>(d_in[3 * t + 0]);
            p.off[t] = reinterpret_cast<const int*>(d_in[3 * t + 1]);
            p.w[t]   = reinterpret_cast<const float*>(d_in[3 * t + 2]);
        }
    }

    tbe_prepare_kernel<<<GRID, BLOCK>>>(p, reinterpret_cast<float*>(d_out));
}